// round 9
// baseline (speedup 1.0000x reference)
#include <cuda_runtime.h>
#include <cstdint>
#include <cstddef>

typedef unsigned long long ull;

#define DEV_INLINE __device__ __forceinline__

DEV_INLINE ull pack2(float lo, float hi) {
    ull r; asm("mov.b64 %0, {%1, %2};" : "=l"(r) : "f"(lo), "f"(hi)); return r;
}
DEV_INLINE unsigned tf32_(float x) {
    unsigned r; asm("cvt.rna.tf32.f32 %0, %1;" : "=r"(r) : "f"(x)); return r;
}
DEV_INLINE void split_(float v, unsigned& hi, unsigned& lo) {
    hi = tf32_(v);
    lo = tf32_(v - __uint_as_float(hi));
}
DEV_INLINE void mma_tf32(float* c, const unsigned* a, unsigned b0, unsigned b1) {
    asm("mma.sync.aligned.m16n8k8.row.col.f32.tf32.tf32.f32 "
        "{%0,%1,%2,%3}, {%4,%5,%6,%7}, {%8,%9}, {%0,%1,%2,%3};"
        : "+f"(c[0]), "+f"(c[1]), "+f"(c[2]), "+f"(c[3])
        : "r"(a[0]), "r"(a[1]), "r"(a[2]), "r"(a[3]), "r"(b0), "r"(b1));
}
// fast sigmoid / tanh (MUFU; rel err ~1e-6)
DEV_INLINE float sigm_(float x) { float e = __expf(-x); return __fdividef(1.f, 1.f + e); }
DEV_INLINE float tanh_(float a) { float t = __expf(-2.f * a); return __fdividef(1.f - t, 1.f + t); }

// ---------------------------------------------------------------------------
// Problem constants
// ---------------------------------------------------------------------------
#define BB 256
#define TT 512
#define HH 256
#define G3 768
#define KP 80

// ---------------------------------------------------------------------------
// Scratch
// ---------------------------------------------------------------------------
__device__ float g_xg[(size_t)BB * TT * G3];
__device__ float g_out0[(size_t)BB * TT * HH];
__device__ float g_hT[BB * HH];
__device__ float g_xpad[(size_t)BB * TT * KP];
__device__ float g_wpad[G3 * KP];

__global__ void pad_k75(const float* __restrict__ src, float* __restrict__ dst, int rows)
{
    int idx = blockIdx.x * blockDim.x + threadIdx.x;
    if (idx >= rows * KP) return;
    int r = idx / KP, c = idx - r * KP;
    dst[idx] = (c < 75) ? src[r * 75 + c] : 0.f;
}

// ---------------------------------------------------------------------------
// tf32 tensor-core GEMM (unchanged from R8, validated)
// ---------------------------------------------------------------------------
#define TSTR 136

__global__ __launch_bounds__(256, 2) void gemm_tf32(
    const float* __restrict__ A, const float* __restrict__ W,
    const float* __restrict__ bias, float* __restrict__ C,
    int M, int N, int K)
{
    __shared__ unsigned As[16][TSTR];
    __shared__ unsigned Bs[16][TSTR];

    const int tid = threadIdx.x;
    const int lane = tid & 31;
    const int wid = tid >> 5;
    const int wm = wid & 1;
    const int wn = wid >> 1;
    const int g  = lane >> 2;
    const int tg = lane & 3;
    const int mb = blockIdx.x * 128;
    const int nb = blockIdx.y * 128;

    const int fr = tid >> 1;
    const int fk = (tid & 1) * 8;

    float c[4][4][4];
#pragma unroll
    for (int i = 0; i < 4; ++i)
#pragma unroll
        for (int j = 0; j < 4; ++j)
#pragma unroll
            for (int q = 0; q < 4; ++q) c[i][j][q] = 0.f;

    for (int k0 = 0; k0 < K; k0 += 16) {
        {
            const float* ap = A + (size_t)(mb + fr) * K + k0 + fk;
            float4 a0 = *(const float4*)(ap);
            float4 a1 = *(const float4*)(ap + 4);
            As[fk + 0][fr] = tf32_(a0.x);
            As[fk + 1][fr] = tf32_(a0.y);
            As[fk + 2][fr] = tf32_(a0.z);
            As[fk + 3][fr] = tf32_(a0.w);
            As[fk + 4][fr] = tf32_(a1.x);
            As[fk + 5][fr] = tf32_(a1.y);
            As[fk + 6][fr] = tf32_(a1.z);
            As[fk + 7][fr] = tf32_(a1.w);
            const float* wp = W + (size_t)(nb + fr) * K + k0 + fk;
            float4 w0 = *(const float4*)(wp);
            float4 w1 = *(const float4*)(wp + 4);
            Bs[fk + 0][fr] = tf32_(w0.x);
            Bs[fk + 1][fr] = tf32_(w0.y);
            Bs[fk + 2][fr] = tf32_(w0.z);
            Bs[fk + 3][fr] = tf32_(w0.w);
            Bs[fk + 4][fr] = tf32_(w1.x);
            Bs[fk + 5][fr] = tf32_(w1.y);
            Bs[fk + 6][fr] = tf32_(w1.z);
            Bs[fk + 7][fr] = tf32_(w1.w);
        }
        __syncthreads();

#pragma unroll
        for (int ks = 0; ks < 2; ++ks) {
            const int kk = ks * 8;
            unsigned bf[4][2];
#pragma unroll
            for (int j = 0; j < 4; ++j) {
                int cb = wn * 32 + j * 8 + g;
                bf[j][0] = Bs[kk + tg][cb];
                bf[j][1] = Bs[kk + tg + 4][cb];
            }
#pragma unroll
            for (int i = 0; i < 4; ++i) {
                int rb = wm * 64 + i * 16;
                unsigned af[4];
                af[0] = As[kk + tg][rb + g];
                af[1] = As[kk + tg][rb + g + 8];
                af[2] = As[kk + tg + 4][rb + g];
                af[3] = As[kk + tg + 4][rb + g + 8];
#pragma unroll
                for (int j = 0; j < 4; ++j)
                    mma_tf32(c[i][j], af, bf[j][0], bf[j][1]);
            }
        }
        __syncthreads();
    }

#pragma unroll
    for (int j = 0; j < 4; ++j) {
        int col = nb + wn * 32 + j * 8 + 2 * tg;
        float2 bb = *(const float2*)(bias + col);
#pragma unroll
        for (int i = 0; i < 4; ++i) {
            int row = mb + wm * 64 + i * 16 + g;
            float2 v0; v0.x = c[i][j][0] + bb.x; v0.y = c[i][j][1] + bb.y;
            float2 v1; v1.x = c[i][j][2] + bb.x; v1.y = c[i][j][3] + bb.y;
            *(float2*)(C + (size_t)row * N + col)       = v0;
            *(float2*)(C + (size_t)(row + 8) * N + col) = v1;
        }
    }
}

// ---------------------------------------------------------------------------
// Tensor-core GRU recurrence.
// 16 clusters x 8 CTAs.  CTA rank owns h-slice [rank*32, rank*32+32),
// i.e. 96 gate rows (r/z/n x 32), K=256, 16 batches (2 n-atoms).
// 12 warps = 6 m16-groups x 2 K-halves; W_hh hi/lo tf32 in registers.
// 3-term mma => fp32-equivalent precision.
// ---------------------------------------------------------------------------
#define CL 8
#define HSTR 24                    // h row: 16 batches + 8 pad (conflict-free)
#define HBUF (256 * HSTR)          // 6144 floats per buffer
#define DSTR 24
#define DHALF (96 * DSTR)          // 2304 floats per K-half
#define REC_SMEM ((2 * HBUF + 2 * DHALF) * 4)   // 67584 B

DEV_INLINE unsigned ctarank() { unsigned r; asm("mov.u32 %0, %%cluster_ctarank;" : "=r"(r)); return r; }
DEV_INLINE unsigned s2u(const void* p) {
    unsigned a;
    asm("{ .reg .u64 t; cvta.to.shared.u64 t, %1; cvt.u32.u64 %0, t; }" : "=r"(a) : "l"(p));
    return a;
}
DEV_INLINE unsigned mapa_(unsigned a, unsigned r) {
    unsigned o; asm("mapa.shared::cluster.u32 %0, %1, %2;" : "=r"(o) : "r"(a), "r"(r)); return o;
}
DEV_INLINE void st_cluster_u64(unsigned addr, ull v) {
    asm volatile("st.shared::cluster.u64 [%0], %1;" :: "r"(addr), "l"(v) : "memory");
}
DEV_INLINE void cl_arrive() { asm volatile("barrier.cluster.arrive.aligned;" ::: "memory"); }
DEV_INLINE void cl_wait()   { asm volatile("barrier.cluster.wait.aligned;"   ::: "memory"); }

__global__ __launch_bounds__(384, 1) void gru_rec_tc(
    const float* __restrict__ xg, const float* __restrict__ W_hh,
    const float* __restrict__ b_hh, float* __restrict__ out_seq,
    float* __restrict__ hT, int layer0)
{
    extern __shared__ float smem[];
    float* hbuf = smem;                 // [2][256][HSTR]
    float* dsm  = smem + 2 * HBUF;      // [2][96][DSTR]

    const int tid  = threadIdx.x;
    const int lane = tid & 31;
    const int wid  = tid >> 5;          // 0..11
    const int g    = lane >> 2;         // 0..7
    const int tg   = lane & 3;          // 0..3
    const int mg   = wid >> 1;          // m16 group 0..5
    const int kh   = wid & 1;           // K-half
    const unsigned rank = ctarank();
    const int cid  = blockIdx.x >> 3;   // cluster 0..15

    // ---- W_hh fragments (hi/lo tf32) into registers ----
    unsigned whi[16][4], wlo[16][4];
    {
        int lr0 = mg * 16 + g;
        int lr1 = lr0 + 8;
        int r0 = (lr0 >> 5) * 256 + (int)rank * 32 + (lr0 & 31);
        int r1 = (lr1 >> 5) * 256 + (int)rank * 32 + (lr1 & 31);
        const float* w0 = W_hh + (size_t)r0 * 256 + kh * 128 + tg;
        const float* w1 = W_hh + (size_t)r1 * 256 + kh * 128 + tg;
#pragma unroll
        for (int i = 0; i < 16; ++i) {
            float v0 = w0[i * 8];
            float v1 = w1[i * 8];
            float v2 = w0[i * 8 + 4];
            float v3 = w1[i * 8 + 4];
            split_(v0, whi[i][0], wlo[i][0]);
            split_(v1, whi[i][1], wlo[i][1]);
            split_(v2, whi[i][2], wlo[i][2]);
            split_(v3, whi[i][3], wlo[i][3]);
        }
    }

    // zero h buffer 0
    for (int i = tid; i < HBUF; i += 384) hbuf[i] = 0.f;

    // gate-pass constants (threads 0..255: 32 h x 8 batch-pairs)
    const int gh  = tid >> 3;             // 0..31 (valid when tid<256)
    const int bp2 = tid & 7;              // batch pair
    const int hglob = (int)rank * 32 + gh;
    float bhr = 0.f, bhz = 0.f, bhn = 0.f;
    if (tid < 256) {
        bhr = b_hh[hglob];
        bhz = b_hh[256 + hglob];
        bhn = b_hh[512 + hglob];
    }
    const int b0g = cid * 16 + 2 * bp2;   // global batch of pair lo

    __syncthreads();
    cl_arrive(); cl_wait();

    const unsigned hbase_u = s2u(hbuf);

    // x prefetch for t=0
    const float* xrow0 = xg + (size_t)b0g * TT * G3;
    const float* xrow1 = xrow0 + (size_t)TT * G3;
    float xr0 = 0, xz0 = 0, xn0 = 0, xr1 = 0, xz1 = 0, xn1 = 0;
    if (tid < 256) {
        xr0 = xrow0[hglob]; xz0 = xrow0[256 + hglob]; xn0 = xrow0[512 + hglob];
        xr1 = xrow1[hglob]; xz1 = xrow1[256 + hglob]; xn1 = xrow1[512 + hglob];
    }

    int p = 0;
    for (int t = 0; t < TT; ++t) {
        const float* hb = hbuf + p * HBUF;

        // ---- HMMA phase (all 12 warps) ----
        float a0[4] = {0.f, 0.f, 0.f, 0.f};   // batches g.. (n-atom 0)
        float a1[4] = {0.f, 0.f, 0.f, 0.f};   // batches 8+g (n-atom 1)
        const float* hk = hb + (kh * 128 + tg) * HSTR + g;
#pragma unroll
        for (int i = 0; i < 16; ++i) {
            float v0 = hk[i * 8 * HSTR];
            float v1 = hk[(i * 8 + 4) * HSTR];
            float v2 = hk[i * 8 * HSTR + 8];
            float v3 = hk[(i * 8 + 4) * HSTR + 8];
            unsigned h0, l0, h1, l1, h2, l2, h3, l3;
            split_(v0, h0, l0);
            split_(v1, h1, l1);
            split_(v2, h2, l2);
            split_(v3, h3, l3);
            mma_tf32(a0, whi[i], h0, h1);
            mma_tf32(a0, whi[i], l0, l1);
            mma_tf32(a0, wlo[i], h0, h1);
            mma_tf32(a1, whi[i], h2, h3);
            mma_tf32(a1, whi[i], l2, l3);
            mma_tf32(a1, wlo[i], h2, h3);
        }

        // ---- stage partial D to smem ----
        {
            float* dst = dsm + kh * DHALF + (mg * 16 + g) * DSTR;
            float2 t0; t0.x = a0[0]; t0.y = a0[1];
            float2 t1; t1.x = a1[0]; t1.y = a1[1];
            float2 t2; t2.x = a0[2]; t2.y = a0[3];
            float2 t3; t3.x = a1[2]; t3.y = a1[3];
            *(float2*)(dst + 2 * tg)              = t0;
            *(float2*)(dst + 8 + 2 * tg)          = t1;
            *(float2*)(dst + 8 * DSTR + 2 * tg)     = t2;
            *(float2*)(dst + 8 * DSTR + 8 + 2 * tg) = t3;
        }
        __syncthreads();

        // ---- gate pass (threads 0..255; 2 batches each) ----
        if (tid < 256) {
            const int co = 2 * bp2;
            const float* d0 = dsm + gh * DSTR + co;               // r, kh0
            const float* d1 = dsm + DHALF + gh * DSTR + co;       // r, kh1
            float2 rA = *(const float2*)(d0);
            float2 rB = *(const float2*)(d1);
            float2 zA = *(const float2*)(d0 + 32 * DSTR);
            float2 zB = *(const float2*)(d1 + 32 * DSTR);
            float2 nA = *(const float2*)(d0 + 64 * DSTR);
            float2 nB = *(const float2*)(d1 + 64 * DSTR);
            float hr0 = rA.x + rB.x, hr1 = rA.y + rB.y;
            float hz0 = zA.x + zB.x, hz1 = zA.y + zB.y;
            float hn0 = nA.x + nB.x, hn1 = nA.y + nB.y;

            float2 hp2 = *(const float2*)(hb + hglob * HSTR + co);

            float r0 = sigm_(xr0 + bhr + hr0);
            float z0 = sigm_(xz0 + bhz + hz0);
            float n0 = tanh_(xn0 + r0 * (hn0 + bhn));
            float hnew0 = (1.f - z0) * n0 + z0 * hp2.x;

            float r1 = sigm_(xr1 + bhr + hr1);
            float z1 = sigm_(xz1 + bhz + hz1);
            float n1 = tanh_(xn1 + r1 * (hn1 + bhn));
            float hnew1 = (1.f - z1) * n1 + z1 * hp2.y;

            ull pair = pack2(hnew0, hnew1);
            unsigned loc = hbase_u + (unsigned)(((1 - p) * HBUF) + hglob * HSTR + co) * 4u;
#pragma unroll
            for (int q = 0; q < CL; ++q)
                st_cluster_u64(mapa_(loc, (unsigned)q), pair);

            if (layer0) {
                out_seq[((size_t)b0g * TT + t) * HH + hglob]       = hnew0;
                out_seq[((size_t)(b0g + 1) * TT + t) * HH + hglob] = hnew1;
            } else if (t == TT - 1) {
                hT[b0g * HH + hglob]       = hnew0;
                hT[(b0g + 1) * HH + hglob] = hnew1;
            }
        }

        cl_arrive();

        // prefetch next x while the cluster barrier settles
        if (tid < 256 && t + 1 < TT) {
            const float* xp0 = xrow0 + (size_t)(t + 1) * G3;
            const float* xp1 = xrow1 + (size_t)(t + 1) * G3;
            xr0 = xp0[hglob]; xz0 = xp0[256 + hglob]; xn0 = xp0[512 + hglob];
            xr1 = xp1[hglob]; xz1 = xp1[256 + hglob]; xn1 = xp1[512 + hglob];
        }

        cl_wait();
        p ^= 1;
    }
}

// ---------------------------------------------------------------------------
// Launch helpers
// ---------------------------------------------------------------------------
static void launch_rec(const float* xg, const float* Whh, const float* bhh,
                       float* oseq, float* hT, int layer0)
{
    cudaFuncSetAttribute(gru_rec_tc, cudaFuncAttributeMaxDynamicSharedMemorySize, REC_SMEM);
    cudaLaunchConfig_t cfg = {};
    cfg.gridDim = dim3(128, 1, 1);
    cfg.blockDim = dim3(384, 1, 1);
    cfg.dynamicSmemBytes = REC_SMEM;
    cfg.stream = 0;
    cudaLaunchAttribute at[1];
    at[0].id = cudaLaunchAttributeClusterDimension;
    at[0].val.clusterDim.x = CL;
    at[0].val.clusterDim.y = 1;
    at[0].val.clusterDim.z = 1;
    cfg.attrs = at;
    cfg.numAttrs = 1;
    cudaLaunchKernelEx(&cfg, gru_rec_tc, xg, Whh, bhh, oseq, hT, layer0);
}

extern "C" void kernel_launch(void* const* d_in, const int* in_sizes, int n_in,
                              void* d_out, int out_size)
{
    const float* x     = (const float*)d_in[0];
    const float* W_ih0 = (const float*)d_in[1];
    const float* W_hh0 = (const float*)d_in[2];
    const float* b_ih0 = (const float*)d_in[3];
    const float* b_hh0 = (const float*)d_in[4];
    const float* W_ih1 = (const float*)d_in[5];
    const float* W_hh1 = (const float*)d_in[6];
    const float* b_ih1 = (const float*)d_in[7];
    const float* b_hh1 = (const float*)d_in[8];
    const float* fc_W  = (const float*)d_in[9];
    const float* fc_b  = (const float*)d_in[10];
    float* out = (float*)d_out;

    float *xg, *o0, *hT, *xp, *wp;
    cudaGetSymbolAddress((void**)&xg, g_xg);
    cudaGetSymbolAddress((void**)&o0, g_out0);
    cudaGetSymbolAddress((void**)&hT, g_hT);
    cudaGetSymbolAddress((void**)&xp, g_xpad);
    cudaGetSymbolAddress((void**)&wp, g_wpad);

    const int M = BB * TT;  // 131072

    pad_k75<<<(M * KP + 255) / 256, 256>>>(x, xp, M);
    pad_k75<<<(G3 * KP + 255) / 256, 256>>>(W_ih0, wp, G3);
    gemm_tf32<<<dim3(M / 128, G3 / 128), 256>>>(xp, wp, b_ih0, xg, M, G3, KP);
    launch_rec(xg, W_hh0, b_hh0, o0, nullptr, 1);
    gemm_tf32<<<dim3(M / 128, G3 / 128), 256>>>(o0, W_ih1, b_ih1, xg, M, G3, 256);
    launch_rec(xg, W_hh1, b_hh1, nullptr, hT, 0);
    gemm_tf32<<<dim3(BB / 128, HH / 128), 256>>>(hT, fc_W, fc_b, out, BB, HH, HH);
}

// round 10
// speedup vs baseline: 1.3008x; 1.3008x over previous
#include <cuda_runtime.h>
#include <cstdint>
#include <cstddef>

typedef unsigned long long ull;

#define DEV_INLINE __device__ __forceinline__

DEV_INLINE ull pack2u(unsigned lo, unsigned hi) {
    ull r; asm("mov.b64 %0, {%1, %2};" : "=l"(r) : "r"(lo), "r"(hi)); return r;
}
DEV_INLINE unsigned tf32_(float x) {
    unsigned r; asm("cvt.rna.tf32.f32 %0, %1;" : "=r"(r) : "f"(x)); return r;
}
DEV_INLINE void split_(float v, unsigned& hi, unsigned& lo) {
    hi = tf32_(v);
    lo = tf32_(v - __uint_as_float(hi));
}
DEV_INLINE void mma_tf32(float* c, const unsigned* a, unsigned b0, unsigned b1) {
    asm("mma.sync.aligned.m16n8k8.row.col.f32.tf32.tf32.f32 "
        "{%0,%1,%2,%3}, {%4,%5,%6,%7}, {%8,%9}, {%0,%1,%2,%3};"
        : "+f"(c[0]), "+f"(c[1]), "+f"(c[2]), "+f"(c[3])
        : "r"(a[0]), "r"(a[1]), "r"(a[2]), "r"(a[3]), "r"(b0), "r"(b1));
}
// fast sigmoid / tanh (MUFU; rel err ~1e-6)
DEV_INLINE float sigm_(float x) { float e = __expf(-x); return __fdividef(1.f, 1.f + e); }
DEV_INLINE float tanh_(float a) { float t = __expf(-2.f * a); return __fdividef(1.f - t, 1.f + t); }

// ---------------------------------------------------------------------------
// Problem constants
// ---------------------------------------------------------------------------
#define BB 256
#define TT 512
#define HH 256
#define G3 768
#define KP 80

// ---------------------------------------------------------------------------
// Scratch
// ---------------------------------------------------------------------------
__device__ float g_xg[(size_t)BB * TT * G3];
__device__ float g_out0[(size_t)BB * TT * HH];
__device__ float g_hT[BB * HH];
__device__ float g_xpad[(size_t)BB * TT * KP];
__device__ float g_wpad[G3 * KP];

__global__ void pad_k75(const float* __restrict__ src, float* __restrict__ dst, int rows)
{
    int idx = blockIdx.x * blockDim.x + threadIdx.x;
    if (idx >= rows * KP) return;
    int r = idx / KP, c = idx - r * KP;
    dst[idx] = (c < 75) ? src[r * 75 + c] : 0.f;
}

// ---------------------------------------------------------------------------
// tf32 tensor-core GEMM (validated)
// ---------------------------------------------------------------------------
#define TSTR 136

__global__ __launch_bounds__(256, 2) void gemm_tf32(
    const float* __restrict__ A, const float* __restrict__ W,
    const float* __restrict__ bias, float* __restrict__ C,
    int M, int N, int K)
{
    __shared__ unsigned As[16][TSTR];
    __shared__ unsigned Bs[16][TSTR];

    const int tid = threadIdx.x;
    const int lane = tid & 31;
    const int wid = tid >> 5;
    const int wm = wid & 1;
    const int wn = wid >> 1;
    const int g  = lane >> 2;
    const int tg = lane & 3;
    const int mb = blockIdx.x * 128;
    const int nb = blockIdx.y * 128;

    const int fr = tid >> 1;
    const int fk = (tid & 1) * 8;

    float c[4][4][4];
#pragma unroll
    for (int i = 0; i < 4; ++i)
#pragma unroll
        for (int j = 0; j < 4; ++j)
#pragma unroll
            for (int q = 0; q < 4; ++q) c[i][j][q] = 0.f;

    for (int k0 = 0; k0 < K; k0 += 16) {
        {
            const float* ap = A + (size_t)(mb + fr) * K + k0 + fk;
            float4 a0 = *(const float4*)(ap);
            float4 a1 = *(const float4*)(ap + 4);
            As[fk + 0][fr] = tf32_(a0.x);
            As[fk + 1][fr] = tf32_(a0.y);
            As[fk + 2][fr] = tf32_(a0.z);
            As[fk + 3][fr] = tf32_(a0.w);
            As[fk + 4][fr] = tf32_(a1.x);
            As[fk + 5][fr] = tf32_(a1.y);
            As[fk + 6][fr] = tf32_(a1.z);
            As[fk + 7][fr] = tf32_(a1.w);
            const float* wp = W + (size_t)(nb + fr) * K + k0 + fk;
            float4 w0 = *(const float4*)(wp);
            float4 w1 = *(const float4*)(wp + 4);
            Bs[fk + 0][fr] = tf32_(w0.x);
            Bs[fk + 1][fr] = tf32_(w0.y);
            Bs[fk + 2][fr] = tf32_(w0.z);
            Bs[fk + 3][fr] = tf32_(w0.w);
            Bs[fk + 4][fr] = tf32_(w1.x);
            Bs[fk + 5][fr] = tf32_(w1.y);
            Bs[fk + 6][fr] = tf32_(w1.z);
            Bs[fk + 7][fr] = tf32_(w1.w);
        }
        __syncthreads();

#pragma unroll
        for (int ks = 0; ks < 2; ++ks) {
            const int kk = ks * 8;
            unsigned bf[4][2];
#pragma unroll
            for (int j = 0; j < 4; ++j) {
                int cb = wn * 32 + j * 8 + g;
                bf[j][0] = Bs[kk + tg][cb];
                bf[j][1] = Bs[kk + tg + 4][cb];
            }
#pragma unroll
            for (int i = 0; i < 4; ++i) {
                int rb = wm * 64 + i * 16;
                unsigned af[4];
                af[0] = As[kk + tg][rb + g];
                af[1] = As[kk + tg][rb + g + 8];
                af[2] = As[kk + tg + 4][rb + g];
                af[3] = As[kk + tg + 4][rb + g + 8];
#pragma unroll
                for (int j = 0; j < 4; ++j)
                    mma_tf32(c[i][j], af, bf[j][0], bf[j][1]);
            }
        }
        __syncthreads();
    }

#pragma unroll
    for (int j = 0; j < 4; ++j) {
        int col = nb + wn * 32 + j * 8 + 2 * tg;
        float2 bb = *(const float2*)(bias + col);
#pragma unroll
        for (int i = 0; i < 4; ++i) {
            int row = mb + wm * 64 + i * 16 + g;
            float2 v0; v0.x = c[i][j][0] + bb.x; v0.y = c[i][j][1] + bb.y;
            float2 v1; v1.x = c[i][j][2] + bb.x; v1.y = c[i][j][3] + bb.y;
            *(float2*)(C + (size_t)row * N + col)       = v0;
            *(float2*)(C + (size_t)(row + 8) * N + col) = v1;
        }
    }
}

// ---------------------------------------------------------------------------
// Tensor-core GRU recurrence (v2).
// 16 clusters x 8 CTAs.  CTA rank owns 32 h (96 gate rows), K=256,
// 16 batches.  W_hh hi/lo tf32 in registers (2-term mma: W exact).
// h is rounded to tf32 ONCE at broadcast; hbuf holds tf32 bits, so the
// HMMA loop is pure LDS+HMMA.  The identity path (z*h) uses the gate
// thread's own fp32 registers — rounding never compounds.
// ---------------------------------------------------------------------------
#define CL 8
#define HSTR 24
#define HBUF (256 * HSTR)
#define DSTR 24
#define DHALF (96 * DSTR)
#define REC_SMEM ((2 * HBUF + 2 * DHALF) * 4)   // 67584 B

DEV_INLINE unsigned ctarank() { unsigned r; asm("mov.u32 %0, %%cluster_ctarank;" : "=r"(r)); return r; }
DEV_INLINE unsigned s2u(const void* p) {
    unsigned a;
    asm("{ .reg .u64 t; cvta.to.shared.u64 t, %1; cvt.u32.u64 %0, t; }" : "=r"(a) : "l"(p));
    return a;
}
DEV_INLINE unsigned mapa_(unsigned a, unsigned r) {
    unsigned o; asm("mapa.shared::cluster.u32 %0, %1, %2;" : "=r"(o) : "r"(a), "r"(r)); return o;
}
DEV_INLINE void st_cluster_u64(unsigned addr, ull v) {
    asm volatile("st.shared::cluster.u64 [%0], %1;" :: "r"(addr), "l"(v) : "memory");
}
DEV_INLINE void cl_arrive() { asm volatile("barrier.cluster.arrive.aligned;" ::: "memory"); }
DEV_INLINE void cl_wait()   { asm volatile("barrier.cluster.wait.aligned;"   ::: "memory"); }

__global__ __launch_bounds__(384, 1) void gru_rec_tc(
    const float* __restrict__ xg, const float* __restrict__ W_hh,
    const float* __restrict__ b_hh, float* __restrict__ out_seq,
    float* __restrict__ hT, int layer0)
{
    extern __shared__ float smem[];
    float* hbuf = smem;                 // [2][256][HSTR]  (tf32 bit patterns)
    float* dsm  = smem + 2 * HBUF;      // [2][96][DSTR]

    const int tid  = threadIdx.x;
    const int lane = tid & 31;
    const int wid  = tid >> 5;
    const int g    = lane >> 2;
    const int tg   = lane & 3;
    const int mg   = wid >> 1;          // m16 group 0..5
    const int kh   = wid & 1;           // K-half
    const unsigned rank = ctarank();
    const int cid  = blockIdx.x >> 3;

    // ---- W_hh fragments (hi/lo tf32) into registers ----
    unsigned whi[16][4], wlo[16][4];
    {
        int lr0 = mg * 16 + g;
        int lr1 = lr0 + 8;
        int r0 = (lr0 >> 5) * 256 + (int)rank * 32 + (lr0 & 31);
        int r1 = (lr1 >> 5) * 256 + (int)rank * 32 + (lr1 & 31);
        const float* w0 = W_hh + (size_t)r0 * 256 + kh * 128 + tg;
        const float* w1 = W_hh + (size_t)r1 * 256 + kh * 128 + tg;
#pragma unroll
        for (int i = 0; i < 16; ++i) {
            split_(w0[i * 8],     whi[i][0], wlo[i][0]);
            split_(w1[i * 8],     whi[i][1], wlo[i][1]);
            split_(w0[i * 8 + 4], whi[i][2], wlo[i][2]);
            split_(w1[i * 8 + 4], whi[i][3], wlo[i][3]);
        }
    }

    for (int i = tid; i < HBUF; i += 384) hbuf[i] = 0.f;

    const int gh  = tid >> 3;
    const int bp2 = tid & 7;
    const int hglob = (int)rank * 32 + gh;
    float bhr = 0.f, bhz = 0.f, bhn = 0.f;
    if (tid < 256) {
        bhr = b_hh[hglob];
        bhz = b_hh[256 + hglob];
        bhn = b_hh[512 + hglob];
    }
    const int b0g = cid * 16 + 2 * bp2;

    __syncthreads();
    cl_arrive(); cl_wait();

    const unsigned hbase_u = s2u(hbuf);

    const float* xrow0 = xg + (size_t)b0g * TT * G3;
    const float* xrow1 = xrow0 + (size_t)TT * G3;
    float xr0 = 0, xz0 = 0, xn0 = 0, xr1 = 0, xz1 = 0, xn1 = 0;
    float hp0 = 0.f, hp1 = 0.f;          // fp32 identity path (own registers)
    if (tid < 256) {
        xr0 = xrow0[hglob]; xz0 = xrow0[256 + hglob]; xn0 = xrow0[512 + hglob];
        xr1 = xrow1[hglob]; xz1 = xrow1[256 + hglob]; xn1 = xrow1[512 + hglob];
    }

    int p = 0;
    for (int t = 0; t < TT; ++t) {
        // ---- HMMA phase: pure LDS + HMMA (h already tf32 in hbuf) ----
        float a0[4] = {0.f, 0.f, 0.f, 0.f};
        float a1[4] = {0.f, 0.f, 0.f, 0.f};
        const unsigned* hk = (const unsigned*)hbuf + p * HBUF + (kh * 128 + tg) * HSTR + g;
#pragma unroll
        for (int i = 0; i < 16; ++i) {
            unsigned u0 = hk[i * 8 * HSTR];
            unsigned u1 = hk[(i * 8 + 4) * HSTR];
            unsigned u2 = hk[i * 8 * HSTR + 8];
            unsigned u3 = hk[(i * 8 + 4) * HSTR + 8];
            mma_tf32(a0, whi[i], u0, u1);
            mma_tf32(a0, wlo[i], u0, u1);
            mma_tf32(a1, whi[i], u2, u3);
            mma_tf32(a1, wlo[i], u2, u3);
        }

        // ---- stage partial D to smem ----
        {
            float* dst = dsm + kh * DHALF + (mg * 16 + g) * DSTR;
            float2 t0; t0.x = a0[0]; t0.y = a0[1];
            float2 t1; t1.x = a1[0]; t1.y = a1[1];
            float2 t2; t2.x = a0[2]; t2.y = a0[3];
            float2 t3; t3.x = a1[2]; t3.y = a1[3];
            *(float2*)(dst + 2 * tg)                = t0;
            *(float2*)(dst + 8 + 2 * tg)            = t1;
            *(float2*)(dst + 8 * DSTR + 2 * tg)     = t2;
            *(float2*)(dst + 8 * DSTR + 8 + 2 * tg) = t3;
        }
        __syncthreads();

        // ---- gate pass (threads 0..255) ----
        if (tid < 256) {
            const int co = 2 * bp2;
            const float* d0 = dsm + gh * DSTR + co;
            const float* d1 = dsm + DHALF + gh * DSTR + co;
            float2 rA = *(const float2*)(d0);
            float2 rB = *(const float2*)(d1);
            float2 zA = *(const float2*)(d0 + 32 * DSTR);
            float2 zB = *(const float2*)(d1 + 32 * DSTR);
            float2 nA = *(const float2*)(d0 + 64 * DSTR);
            float2 nB = *(const float2*)(d1 + 64 * DSTR);
            float hr0 = rA.x + rB.x, hr1 = rA.y + rB.y;
            float hz0 = zA.x + zB.x, hz1 = zA.y + zB.y;
            float hn0 = nA.x + nB.x, hn1 = nA.y + nB.y;

            float r0 = sigm_(xr0 + bhr + hr0);
            float z0 = sigm_(xz0 + bhz + hz0);
            float n0 = tanh_(xn0 + r0 * (hn0 + bhn));
            float hnew0 = (1.f - z0) * n0 + z0 * hp0;

            float r1 = sigm_(xr1 + bhr + hr1);
            float z1 = sigm_(xz1 + bhz + hz1);
            float n1 = tanh_(xn1 + r1 * (hn1 + bhn));
            float hnew1 = (1.f - z1) * n1 + z1 * hp1;

            hp0 = hnew0;
            hp1 = hnew1;

            // round ONCE to tf32, broadcast bits to all 8 cluster CTAs
            ull pair = pack2u(tf32_(hnew0), tf32_(hnew1));
            unsigned loc = hbase_u + (unsigned)(((1 - p) * HBUF) + hglob * HSTR + co) * 4u;
#pragma unroll
            for (int q = 0; q < CL; ++q)
                st_cluster_u64(mapa_(loc, (unsigned)q), pair);

            if (layer0) {
                out_seq[((size_t)b0g * TT + t) * HH + hglob]       = hnew0;
                out_seq[((size_t)(b0g + 1) * TT + t) * HH + hglob] = hnew1;
            } else if (t == TT - 1) {
                hT[b0g * HH + hglob]       = hnew0;
                hT[(b0g + 1) * HH + hglob] = hnew1;
            }
        }

        cl_arrive();

        if (tid < 256 && t + 1 < TT) {
            const float* xp0 = xrow0 + (size_t)(t + 1) * G3;
            const float* xp1 = xrow1 + (size_t)(t + 1) * G3;
            xr0 = xp0[hglob]; xz0 = xp0[256 + hglob]; xn0 = xp0[512 + hglob];
            xr1 = xp1[hglob]; xz1 = xp1[256 + hglob]; xn1 = xp1[512 + hglob];
        }

        cl_wait();
        p ^= 1;
    }
}

// ---------------------------------------------------------------------------
// Launch helpers
// ---------------------------------------------------------------------------
static void launch_rec(const float* xg, const float* Whh, const float* bhh,
                       float* oseq, float* hT, int layer0)
{
    cudaFuncSetAttribute(gru_rec_tc, cudaFuncAttributeMaxDynamicSharedMemorySize, REC_SMEM);
    cudaLaunchConfig_t cfg = {};
    cfg.gridDim = dim3(128, 1, 1);
    cfg.blockDim = dim3(384, 1, 1);
    cfg.dynamicSmemBytes = REC_SMEM;
    cfg.stream = 0;
    cudaLaunchAttribute at[1];
    at[0].id = cudaLaunchAttributeClusterDimension;
    at[0].val.clusterDim.x = CL;
    at[0].val.clusterDim.y = 1;
    at[0].val.clusterDim.z = 1;
    cfg.attrs = at;
    cfg.numAttrs = 1;
    cudaLaunchKernelEx(&cfg, gru_rec_tc, xg, Whh, bhh, oseq, hT, layer0);
}

extern "C" void kernel_launch(void* const* d_in, const int* in_sizes, int n_in,
                              void* d_out, int out_size)
{
    const float* x     = (const float*)d_in[0];
    const float* W_ih0 = (const float*)d_in[1];
    const float* W_hh0 = (const float*)d_in[2];
    const float* b_ih0 = (const float*)d_in[3];
    const float* b_hh0 = (const float*)d_in[4];
    const float* W_ih1 = (const float*)d_in[5];
    const float* W_hh1 = (const float*)d_in[6];
    const float* b_ih1 = (const float*)d_in[7];
    const float* b_hh1 = (const float*)d_in[8];
    const float* fc_W  = (const float*)d_in[9];
    const float* fc_b  = (const float*)d_in[10];
    float* out = (float*)d_out;

    float *xg, *o0, *hT, *xp, *wp;
    cudaGetSymbolAddress((void**)&xg, g_xg);
    cudaGetSymbolAddress((void**)&o0, g_out0);
    cudaGetSymbolAddress((void**)&hT, g_hT);
    cudaGetSymbolAddress((void**)&xp, g_xpad);
    cudaGetSymbolAddress((void**)&wp, g_wpad);

    const int M = BB * TT;  // 131072

    pad_k75<<<(M * KP + 255) / 256, 256>>>(x, xp, M);
    pad_k75<<<(G3 * KP + 255) / 256, 256>>>(W_ih0, wp, G3);
    gemm_tf32<<<dim3(M / 128, G3 / 128), 256>>>(xp, wp, b_ih0, xg, M, G3, KP);
    launch_rec(xg, W_hh0, b_hh0, o0, nullptr, 1);
    gemm_tf32<<<dim3(M / 128, G3 / 128), 256>>>(o0, W_ih1, b_ih1, xg, M, G3, 256);
    launch_rec(xg, W_hh1, b_hh1, nullptr, hT, 0);
    gemm_tf32<<<dim3(BB / 128, HH / 128), 256>>>(hT, fc_W, fc_b, out, BB, HH, HH);
}